// round 13
// baseline (speedup 1.0000x reference)
#include <cuda_runtime.h>
#include <cstdint>

// HELoss: loss = mean_i [ logsumexp_j(s*logits[i,j] with label col -> s*(l_y - cm)) - s*(l_y - cm) ]
// N=8192 rows, C=32000 cols, s=30. HBM-bound streaming row-LSE.
// R13 = R12 (single kernel, no-stall RED epilogue, block-0 finalizer)
//     + __launch_bounds__(256, 4): pin the 4-blocks/SM register point so the
//       8-deep float4 pipeline survives (R12 silently clamped to 32 regs).

constexpr int N_ROWS = 8192;
constexpr int N_COLS = 32000;
constexpr int NVEC   = N_COLS / 4;      // 8000 float4 per row
constexpr float S_SCALE = 30.0f;
constexpr float K_L2E   = 30.0f * 1.44269504088896340736f; // S * log2(e)
constexpr float LN2F    = 0.693147180559945309f;
constexpr float NEG_BIG = -3.402823466e38f;
constexpr double FIXED_SCALE = 4294967296.0;   // 2^32

__device__ unsigned long long g_acc  = 0ull;   // fixed-point loss accumulator
__device__ unsigned int       g_done = 0u;     // completed-row counter

static __device__ __forceinline__ float ex2f_(float x) {
    float y; asm("ex2.approx.ftz.f32 %0, %1;" : "=f"(y) : "f"(x)); return y;
}
static __device__ __forceinline__ float lg2f_(float x) {
    float y; asm("lg2.approx.ftz.f32 %0, %1;" : "=f"(y) : "f"(x)); return y;
}

// Fire-and-forget relaxed reduction (data): RED.ADD.64, no return, no wait.
static __device__ __forceinline__ void red_add_u64_relaxed(unsigned long long* p,
                                                           unsigned long long v) {
    asm volatile("red.relaxed.gpu.global.add.u64 [%0], %1;"
                 :: "l"(p), "l"(v) : "memory");
}

// No-return RELEASE reduction (counter): orders the prior data-RED at L2;
// the issuing warp does NOT wait (unlike atom-with-return).
static __device__ __forceinline__ void red_add_u32_release(unsigned int* p,
                                                           unsigned int v) {
    asm volatile("red.release.gpu.global.add.u32 [%0], %1;"
                 :: "l"(p), "r"(v) : "memory");
}

static __device__ __forceinline__ unsigned int acquire_load_u32(const unsigned int* p) {
    unsigned int v;
    asm volatile("ld.acquire.gpu.global.u32 %0, [%1];"
                 : "=r"(v) : "l"(p) : "memory");
    return v;
}

static __device__ __forceinline__ unsigned long long acquire_load_u64(const unsigned long long* p) {
    unsigned long long v;
    asm volatile("ld.acquire.gpu.global.u64 %0, [%1];"
                 : "=l"(v) : "l"(p) : "memory");
    return v;
}

// Load the 4 float4 for iteration `it` (only the very last vector needs a guard).
static __device__ __forceinline__ void load_iter(const float4* __restrict__ vp,
                                                 int tid, int it, float4 v[4]) {
    const int idx0 = tid + it * 1024;
    #pragma unroll
    for (int j = 0; j < 4; ++j) {
        const int idx = idx0 + j * 256;
        if ((it * 4 + j + 1) * 256 <= NVEC) {
            v[j] = vp[idx];                       // compile-time safe
        } else {
            if (idx < NVEC) v[j] = vp[idx];       // only last load guarded
            else            v[j] = make_float4(NEG_BIG, NEG_BIG, NEG_BIG, NEG_BIG);
        }
    }
}

static __device__ __forceinline__ void consume_iter(const float4 v[4],
                                                    float& m, float& s) {
    float a0 = fmaxf(fmaxf(v[0].x, v[0].y), fmaxf(v[0].z, v[0].w));
    float a1 = fmaxf(fmaxf(v[1].x, v[1].y), fmaxf(v[1].z, v[1].w));
    float a2 = fmaxf(fmaxf(v[2].x, v[2].y), fmaxf(v[2].z, v[2].w));
    float a3 = fmaxf(fmaxf(v[3].x, v[3].y), fmaxf(v[3].z, v[3].w));
    float cmx = fmaxf(fmaxf(a0, a1), fmaxf(a2, a3));
    float nm = fmaxf(m, cmx);
    float scale = ex2f_((m - nm) * K_L2E);  // ==1 when max unchanged
    m = nm;
    const float nmK = -m * K_L2E;
    float e00 = ex2f_(fmaf(v[0].x, K_L2E, nmK));
    float e01 = ex2f_(fmaf(v[0].y, K_L2E, nmK));
    float e02 = ex2f_(fmaf(v[0].z, K_L2E, nmK));
    float e03 = ex2f_(fmaf(v[0].w, K_L2E, nmK));
    float e10 = ex2f_(fmaf(v[1].x, K_L2E, nmK));
    float e11 = ex2f_(fmaf(v[1].y, K_L2E, nmK));
    float e12 = ex2f_(fmaf(v[1].z, K_L2E, nmK));
    float e13 = ex2f_(fmaf(v[1].w, K_L2E, nmK));
    float e20 = ex2f_(fmaf(v[2].x, K_L2E, nmK));
    float e21 = ex2f_(fmaf(v[2].y, K_L2E, nmK));
    float e22 = ex2f_(fmaf(v[2].z, K_L2E, nmK));
    float e23 = ex2f_(fmaf(v[2].w, K_L2E, nmK));
    float e30 = ex2f_(fmaf(v[3].x, K_L2E, nmK));
    float e31 = ex2f_(fmaf(v[3].y, K_L2E, nmK));
    float e32 = ex2f_(fmaf(v[3].z, K_L2E, nmK));
    float e33 = ex2f_(fmaf(v[3].w, K_L2E, nmK));
    float t0 = (e00 + e01) + (e02 + e03);
    float t1 = (e10 + e11) + (e12 + e13);
    float t2 = (e20 + e21) + (e22 + e23);
    float t3 = (e30 + e31) + (e32 + e33);
    float csum = (t0 + t1) + (t2 + t3);
    s = fmaf(s, scale, csum);
}

__global__ void __launch_bounds__(256, 4)   // pin 4 blocks/SM: reg budget 64
heloss_kernel(const float* __restrict__ logits,
              const unsigned int* __restrict__ labels_raw,
              const float* __restrict__ cm_ptr,
              float* __restrict__ out) {
    // ---- Block 0: finalizer (cold path, wave-1 resident, cheap poll) ----
    if (blockIdx.x == 0) {
        if (threadIdx.x == 0) {
            while (acquire_load_u32(&g_done) != (unsigned)N_ROWS)
                __nanosleep(128);
            // All 8192 release-REDs observed -> all data-REDs visible.
            double v = (double)(long long)acquire_load_u64(&g_acc);
            out[0] = (float)(v * (1.0 / FIXED_SCALE) * (1.0 / (double)N_ROWS));
            g_done = 0u;    // reset for next graph replay (kernel-end flush)
            g_acc  = 0ull;
        }
        return;
    }

    // ---- Worker blocks: one row each (row = blockIdx.x - 1) ----
    const int row = blockIdx.x - 1;
    const int tid = threadIdx.x;

    const float* rowp = logits + (size_t)row * N_COLS;
    const float4* vp  = (const float4*)rowp;

    float m = NEG_BIG;
    float s = 0.0f;

    // Software pipeline: prefetch depth 1 -> per-warp 8 outstanding LDG.128.
    float4 cur[4], nxt[4];
    load_iter(vp, tid, 0, cur);
    #pragma unroll
    for (int it = 0; it < 8; ++it) {
        if (it < 7) load_iter(vp, tid, it + 1, nxt);
        consume_iter(cur, m, s);
        if (it < 7) {
            cur[0] = nxt[0]; cur[1] = nxt[1]; cur[2] = nxt[2]; cur[3] = nxt[3];
        }
    }

    // warp combine (m, s)
    #pragma unroll
    for (int o = 16; o > 0; o >>= 1) {
        float mo = __shfl_down_sync(0xffffffffu, m, o);
        float so = __shfl_down_sync(0xffffffffu, s, o);
        float M  = fmaxf(m, mo);
        s = s * ex2f_((m - M) * K_L2E) + so * ex2f_((mo - M) * K_L2E);
        m = M;
    }

    __shared__ float sm_m[8];
    __shared__ float sm_s[8];
    const int wid = tid >> 5;
    if ((tid & 31) == 0) { sm_m[wid] = m; sm_s[wid] = s; }
    __syncthreads();

    if (tid < 32) {
        float m2 = (tid < 8) ? sm_m[tid] : NEG_BIG;
        float s2 = (tid < 8) ? sm_s[tid] : 0.0f;
        #pragma unroll
        for (int o = 4; o > 0; o >>= 1) {
            float mo = __shfl_down_sync(0xffffffffu, m2, o);
            float so = __shfl_down_sync(0xffffffffu, s2, o);
            float M  = fmaxf(m2, mo);
            s2 = s2 * ex2f_((m2 - M) * K_L2E) + so * ex2f_((mo - M) * K_L2E);
            m2 = M;
        }

        // In-warp label-width detection: int64 little-endian labels (< 32000)
        // have all-zero odd 32-bit words. False-positive prob for int32 random
        // labels ~ (1/32000)^32 ~= 0. L2-broadcast reads.
        unsigned int oddw = labels_raw[2 * tid + 1];
        unsigned int mask = __ballot_sync(0xffffffffu, oddw == 0u);
        if (tid == 0) {
            const bool is64 = (mask == 0xffffffffu);
            int lab;
            if (is64) lab = (int)((const long long*)labels_raw)[row];
            else      lab = ((const int*)labels_raw)[row];

            const float cm = __ldg(cm_ptr);
            const float a  = __ldg(rowp + lab);   // raw label logit
            const float ap = a - cm;              // substituted value
            // Post-hoc LSE correction: swap exp(K*a) term for exp(K*ap).
            // Bitwise no-op when cm == 0.
            const float M  = fmaxf(m2, ap);
            const float sc = ex2f_((m2 - M) * K_L2E);
            float sp = fmaf(s2, sc, ex2f_((ap - M) * K_L2E) - ex2f_((a - M) * K_L2E));
            const float lse = S_SCALE * M + lg2f_(sp) * LN2F;  // natural-log LSE
            const float loss = lse - S_SCALE * ap;             // >= 0 always

            // Data: relaxed fire-and-forget RED (associative fixed point).
            long long q = __double2ll_rn((double)loss * FIXED_SCALE);
            red_add_u64_relaxed(&g_acc, (unsigned long long)q);
            // Completion: no-return RELEASE RED — orders the data-RED above;
            // the warp does not wait (no drain stall).
            red_add_u32_release(&g_done, 1u);
        }
    }
}

extern "C" void kernel_launch(void* const* d_in, const int* in_sizes, int n_in,
                              void* d_out, int out_size) {
    const float* logits = (const float*)d_in[0];
    const unsigned int* labels = (const unsigned int*)d_in[1];
    const float* cm     = (const float*)d_in[2];
    float* out = (float*)d_out;

    heloss_kernel<<<N_ROWS + 1, 256>>>(logits, labels, cm, out);
}

// round 14
// speedup vs baseline: 1.0447x; 1.0447x over previous
#include <cuda_runtime.h>
#include <cstdint>

// HELoss: loss = mean_i [ logsumexp_j(s*logits[i,j] with label col -> s*(l_y - cm)) - s*(l_y - cm) ]
// N=8192 rows, C=32000 cols, s=30. HBM-bound streaming row-LSE (~91% of spec).
// FINAL (= R9, re-validated): streaming kernel with software-pipelined float4
// loads + fire-and-forget fixed-point RED.ADD.64 (order-independent -> bitwise
// deterministic), finalized by a <<<1,1>>> PDL secondary.
// Falsified alternatives: gpu-fence fusion (+19us, CCTL.IVALL), atom-with-return
// fusion (+14..22us, epilogue drain stall), RED-fusion (+2us, loop reconfig),
// early-trigger PDL spin (+2.6us), evict_first/LDG.256 (neutral),
// minblocks pinning (regs/occ trade is flat at the DRAM wall).

constexpr int N_ROWS = 8192;
constexpr int N_COLS = 32000;
constexpr int NVEC   = N_COLS / 4;      // 8000 float4 per row
constexpr float S_SCALE = 30.0f;
constexpr float K_L2E   = 30.0f * 1.44269504088896340736f; // S * log2(e)
constexpr float LN2F    = 0.693147180559945309f;
constexpr float NEG_BIG = -3.402823466e38f;
constexpr double FIXED_SCALE = 4294967296.0;   // 2^32

__device__ unsigned long long g_acc = 0ull;    // fixed-point loss accumulator

static __device__ __forceinline__ float ex2f_(float x) {
    float y; asm("ex2.approx.ftz.f32 %0, %1;" : "=f"(y) : "f"(x)); return y;
}
static __device__ __forceinline__ float lg2f_(float x) {
    float y; asm("lg2.approx.ftz.f32 %0, %1;" : "=f"(y) : "f"(x)); return y;
}

// Fire-and-forget relaxed reduction: lowers to RED.ADD.64 (no return, no wait).
static __device__ __forceinline__ void red_add_u64(unsigned long long* p,
                                                   unsigned long long v) {
    asm volatile("red.relaxed.gpu.global.add.u64 [%0], %1;"
                 :: "l"(p), "l"(v) : "memory");
}

// Load the 4 float4 for iteration `it` (only the very last vector needs a guard).
static __device__ __forceinline__ void load_iter(const float4* __restrict__ vp,
                                                 int tid, int it, float4 v[4]) {
    const int idx0 = tid + it * 1024;
    #pragma unroll
    for (int j = 0; j < 4; ++j) {
        const int idx = idx0 + j * 256;
        if ((it * 4 + j + 1) * 256 <= NVEC) {
            v[j] = vp[idx];                       // compile-time safe
        } else {
            if (idx < NVEC) v[j] = vp[idx];       // only last load guarded
            else            v[j] = make_float4(NEG_BIG, NEG_BIG, NEG_BIG, NEG_BIG);
        }
    }
}

static __device__ __forceinline__ void consume_iter(const float4 v[4],
                                                    float& m, float& s) {
    float a0 = fmaxf(fmaxf(v[0].x, v[0].y), fmaxf(v[0].z, v[0].w));
    float a1 = fmaxf(fmaxf(v[1].x, v[1].y), fmaxf(v[1].z, v[1].w));
    float a2 = fmaxf(fmaxf(v[2].x, v[2].y), fmaxf(v[2].z, v[2].w));
    float a3 = fmaxf(fmaxf(v[3].x, v[3].y), fmaxf(v[3].z, v[3].w));
    float cmx = fmaxf(fmaxf(a0, a1), fmaxf(a2, a3));
    float nm = fmaxf(m, cmx);
    float scale = ex2f_((m - nm) * K_L2E);  // ==1 when max unchanged
    m = nm;
    const float nmK = -m * K_L2E;
    float e00 = ex2f_(fmaf(v[0].x, K_L2E, nmK));
    float e01 = ex2f_(fmaf(v[0].y, K_L2E, nmK));
    float e02 = ex2f_(fmaf(v[0].z, K_L2E, nmK));
    float e03 = ex2f_(fmaf(v[0].w, K_L2E, nmK));
    float e10 = ex2f_(fmaf(v[1].x, K_L2E, nmK));
    float e11 = ex2f_(fmaf(v[1].y, K_L2E, nmK));
    float e12 = ex2f_(fmaf(v[1].z, K_L2E, nmK));
    float e13 = ex2f_(fmaf(v[1].w, K_L2E, nmK));
    float e20 = ex2f_(fmaf(v[2].x, K_L2E, nmK));
    float e21 = ex2f_(fmaf(v[2].y, K_L2E, nmK));
    float e22 = ex2f_(fmaf(v[2].z, K_L2E, nmK));
    float e23 = ex2f_(fmaf(v[2].w, K_L2E, nmK));
    float e30 = ex2f_(fmaf(v[3].x, K_L2E, nmK));
    float e31 = ex2f_(fmaf(v[3].y, K_L2E, nmK));
    float e32 = ex2f_(fmaf(v[3].z, K_L2E, nmK));
    float e33 = ex2f_(fmaf(v[3].w, K_L2E, nmK));
    float t0 = (e00 + e01) + (e02 + e03);
    float t1 = (e10 + e11) + (e12 + e13);
    float t2 = (e20 + e21) + (e22 + e23);
    float t3 = (e30 + e31) + (e32 + e33);
    float csum = (t0 + t1) + (t2 + t3);
    s = fmaf(s, scale, csum);
}

__global__ void __launch_bounds__(256)
row_lse_kernel(const float* __restrict__ logits,
               const unsigned int* __restrict__ labels_raw,
               const float* __restrict__ cm_ptr) {
    const int row = blockIdx.x;
    const int tid = threadIdx.x;

    const float* rowp = logits + (size_t)row * N_COLS;
    const float4* vp  = (const float4*)rowp;

    float m = NEG_BIG;
    float s = 0.0f;

    // Software pipeline: prefetch depth 1 -> per-warp 8 outstanding LDG.128.
    float4 cur[4], nxt[4];
    load_iter(vp, tid, 0, cur);
    #pragma unroll
    for (int it = 0; it < 8; ++it) {
        if (it < 7) load_iter(vp, tid, it + 1, nxt);
        consume_iter(cur, m, s);
        if (it < 7) {
            cur[0] = nxt[0]; cur[1] = nxt[1]; cur[2] = nxt[2]; cur[3] = nxt[3];
        }
    }

    // warp combine (m, s)
    #pragma unroll
    for (int o = 16; o > 0; o >>= 1) {
        float mo = __shfl_down_sync(0xffffffffu, m, o);
        float so = __shfl_down_sync(0xffffffffu, s, o);
        float M  = fmaxf(m, mo);
        s = s * ex2f_((m - M) * K_L2E) + so * ex2f_((mo - M) * K_L2E);
        m = M;
    }

    __shared__ float sm_m[8];
    __shared__ float sm_s[8];
    const int wid = tid >> 5;
    if ((tid & 31) == 0) { sm_m[wid] = m; sm_s[wid] = s; }
    __syncthreads();

    if (tid < 32) {
        float m2 = (tid < 8) ? sm_m[tid] : NEG_BIG;
        float s2 = (tid < 8) ? sm_s[tid] : 0.0f;
        #pragma unroll
        for (int o = 4; o > 0; o >>= 1) {
            float mo = __shfl_down_sync(0xffffffffu, m2, o);
            float so = __shfl_down_sync(0xffffffffu, s2, o);
            float M  = fmaxf(m2, mo);
            s2 = s2 * ex2f_((m2 - M) * K_L2E) + so * ex2f_((mo - M) * K_L2E);
            m2 = M;
        }

        // In-warp label-width detection: int64 little-endian labels (< 32000)
        // have all-zero odd 32-bit words. False-positive prob for int32 random
        // labels ~ (1/32000)^32 ~= 0. L2-broadcast reads.
        unsigned int oddw = labels_raw[2 * tid + 1];
        unsigned int mask = __ballot_sync(0xffffffffu, oddw == 0u);
        if (tid == 0) {
            const bool is64 = (mask == 0xffffffffu);
            int lab;
            if (is64) lab = (int)((const long long*)labels_raw)[row];
            else      lab = ((const int*)labels_raw)[row];

            const float cm = __ldg(cm_ptr);
            const float a  = __ldg(rowp + lab);   // raw label logit (hot)
            const float ap = a - cm;              // substituted value
            // Post-hoc LSE correction: swap exp(K*a) term for exp(K*ap).
            // Bitwise no-op when cm == 0.
            const float M  = fmaxf(m2, ap);
            const float sc = ex2f_((m2 - M) * K_L2E);
            float sp = fmaf(s2, sc, ex2f_((ap - M) * K_L2E) - ex2f_((a - M) * K_L2E));
            const float lse = S_SCALE * M + lg2f_(sp) * LN2F;  // natural-log LSE
            const float loss = lse - S_SCALE * ap;             // >= 0 always

            // Deterministic accumulation: fixed-point (2^-32) integer RED —
            // associative, order-independent, NO ordering semantics -> no
            // write-drain stall, no return wait. Thread 0 does not block.
            long long q = __double2ll_rn((double)loss * FIXED_SCALE);
            red_add_u64(&g_acc, (unsigned long long)q);
        }
    }
}

__global__ void finalize_kernel(float* __restrict__ out) {
    // PDL: launch overlaps the primary's tail; the grid-dependency sync plus
    // the primary's kernel-completion flush make all REDs visible here.
    cudaGridDependencySynchronize();
    double v = (double)(long long)g_acc;
    out[0] = (float)(v * (1.0 / FIXED_SCALE) * (1.0 / (double)N_ROWS));
    g_acc = 0ull;   // reset for the next graph replay (stream-ordered)
}

extern "C" void kernel_launch(void* const* d_in, const int* in_sizes, int n_in,
                              void* d_out, int out_size) {
    const float* logits = (const float*)d_in[0];
    const unsigned int* labels = (const unsigned int*)d_in[1];
    const float* cm     = (const float*)d_in[2];
    float* out = (float*)d_out;

    row_lse_kernel<<<N_ROWS, 256>>>(logits, labels, cm);

    // Single-thread finalizer as a PDL secondary: launch latency hides under
    // the primary's last wave; actual work is ~10 instructions.
    cudaLaunchConfig_t cfg = {};
    cfg.gridDim  = dim3(1, 1, 1);
    cfg.blockDim = dim3(1, 1, 1);
    cfg.dynamicSmemBytes = 0;
    cudaLaunchAttribute attrs[1];
    attrs[0].id = cudaLaunchAttributeProgrammaticStreamSerialization;
    attrs[0].val.programmaticStreamSerializationAllowed = 1;
    cfg.attrs = attrs;
    cfg.numAttrs = 1;
    cudaLaunchKernelEx(&cfg, finalize_kernel, out);
}